// round 17
// baseline (speedup 1.0000x reference)
#include <cuda_runtime.h>

// Grad3D: out = |dx| + |dy| + |dz| with central differences, zero-padded.
// x shape (4, 1, 192, 224, 192) fp32, contiguous.
// R16 structure (register D-march, prefetch distance 3, smem double buffer,
// one barrier per plane) with fully incremental addressing: running src/dst
// pointers, swapped smem bases, uniform prefetch cutoff. No per-iter IMADs.

#define Nn 4
#define Dd 192
#define Hh 224
#define Ww 192
#define HW (Hh * Ww)          // 43008
#define DHW (Dd * HW)         // 8257536

#define BH 8                  // H output rows per block
#define DCHUNK 16             // D planes per block
#define NROWS (BH + 2)        // incl. halo rows (10)
#define ROWSTRIDE 200         // floats/row (800B): [3]=zero(w=-1), [4..195]=data, [196]=zero(w=192)
#define QPERROW (Ww / 4)      // 48
#define THREADS (NROWS * QPERROW)  // 480

__global__ void __launch_bounds__(THREADS, 3)
grad3d_kernel(const float* __restrict__ x, float* __restrict__ out)
{
    __shared__ __align__(16) float sm[2][NROWS * ROWSTRIDE];

    const int tid  = threadIdx.x;
    const int r    = tid / QPERROW;       // 0..9 (r=0, r=9 are halo rows)
    const int q    = tid - r * QPERROW;   // 0..47
    const int h0   = blockIdx.x * BH;     // 0..216
    const int d0   = blockIdx.y * DCHUNK; // 0..176
    const int n    = blockIdx.z;
    const int gh   = h0 - 1 + r;
    const bool inH  = (gh >= 0) && (gh < Hh);
    const bool comp = (r >= 1) && (r <= BH);

    // Zero guard columns (w=-1 at [3], w=W at [196]) in both buffers.
    if (q == 0) {
        sm[0][r * ROWSTRIDE + 3] = 0.0f;
        sm[0][r * ROWSTRIDE + 4 + Ww] = 0.0f;
        sm[1][r * ROWSTRIDE + 3] = 0.0f;
        sm[1][r * ROWSTRIDE + 4 + Ww] = 0.0f;
    }

    // srcp tracks plane d (loop plane); loads in the loop are at +3*HW.
    const float* __restrict__ srcp =
        x + (size_t)n * DHW + (size_t)(inH ? gh : 0) * Ww + q * 4 + (size_t)d0 * HW;
    float* __restrict__ dstp =
        out + (size_t)n * DHW + (size_t)(comp ? gh : 0) * Ww + q * 4 + (size_t)d0 * HW;

    const int soff = r * ROWSTRIDE + 4 + q * 4;
    float* smA = &sm[d0 & 1][soff];         // buffer holding plane d (current)
    float* smB = &sm[(d0 + 1) & 1][soff];   // buffer for plane d+1

    const float4 Z = make_float4(0.f, 0.f, 0.f, 0.f);

    // Last k for which a prefetch of plane d0+k+3 is valid & useful:
    // need d0+k+3 <= min(d0+DCHUNK, Dd-1).
    const int klast = ((d0 + DCHUNK < Dd) ? DCHUNK : (Dd - 1 - d0)) - 3;

    // Prologue loads: planes d0-1 .. d0+2 (bounds-checked).
    float4 pv = (inH && d0 > 0)      ? *reinterpret_cast<const float4*>(srcp - HW)     : Z;
    float4 cu = inH                  ? *reinterpret_cast<const float4*>(srcp)          : Z;
    float4 nx = inH                  ? *reinterpret_cast<const float4*>(srcp + HW)     : Z;  // d0+1 <= 177
    float4 n2 = inH                  ? *reinterpret_cast<const float4*>(srcp + 2 * HW) : Z;  // d0+2 <= 178
    *reinterpret_cast<float4*>(smA) = cu;
    __syncthreads();

    for (int k = 0; k < DCHUNK; ++k) {
        // Prefetch plane d+3 (consumed as nx two rotations later).
        float4 tmp = (inH && k <= klast) ? *reinterpret_cast<const float4*>(srcp + 3 * HW) : Z;

        // Publish plane d+1 for next iteration's neighbor reads.
        if (k + 1 < DCHUNK)
            *reinterpret_cast<float4*>(smB) = nx;

        if (comp) {
            float  lf = smA[-1];                                          // guard at q==0
            float  rt = smA[4];                                           // guard at q==47
            float4 up = *reinterpret_cast<const float4*>(smA - ROWSTRIDE);
            float4 dn = *reinterpret_cast<const float4*>(smA + ROWSTRIDE);

            float4 o;
            o.x = 0.5f * (fabsf(cu.y - lf)   + fabsf(dn.x - up.x) + fabsf(nx.x - pv.x));
            o.y = 0.5f * (fabsf(cu.z - cu.x) + fabsf(dn.y - up.y) + fabsf(nx.y - pv.y));
            o.z = 0.5f * (fabsf(cu.w - cu.y) + fabsf(dn.z - up.z) + fabsf(nx.z - pv.z));
            o.w = 0.5f * (fabsf(rt   - cu.z) + fabsf(dn.w - up.w) + fabsf(nx.w - pv.w));

            *reinterpret_cast<float4*>(dstp) = o;
        }

        __syncthreads();   // smB published; reads of smA complete
        pv = cu; cu = nx; nx = n2; n2 = tmp;
        { float* t = smA; smA = smB; smB = t; }
        srcp += HW;
        dstp += HW;
    }
}

extern "C" void kernel_launch(void* const* d_in, const int* in_sizes, int n_in,
                              void* d_out, int out_size)
{
    const float* x = (const float*)d_in[0];
    float* out = (float*)d_out;
    dim3 grid(Hh / BH, Dd / DCHUNK, Nn);   // 28 x 12 x 4 = 1344 blocks
    grad3d_kernel<<<grid, THREADS>>>(x, out);
}